// round 15
// baseline (speedup 1.0000x reference)
#include <cuda_runtime.h>
#include <cuda_bf16.h>
#include <math.h>
#include <cstdint>

#define T_  4096
#define NF_ 256
#define DH_ 64
#define BH_ 64
#define DS  0.35355339059327373f
#define DNC 0.0625f

// per-xb partial ctx: [xb=16][bh][e'=72][j=256] (only e<65 written/read)
__device__ float g_ctx_part[16 * BH_ * 72 * NF_];
// precomputed bf16 smem-images
__device__ uint4 g_proj_hi[2048], g_proj_lo[2048];            // 32KB each
__device__ uint4 g_ctx_hi[BH_ * 2048], g_ctx_lo[BH_ * 2048];  // 32KB per bh
__device__ float g_ksum[BH_ * NF_];

__device__ __forceinline__ uint32_t smem_u32(const void* p) {
  uint32_t a;
  asm("{ .reg .u64 tmp; cvta.to.shared.u64 tmp, %1; cvt.u32.u64 %0, tmp; }"
      : "=r"(a) : "l"(p));
  return a;
}

__device__ __forceinline__ void ldmx4(uint32_t* r, uint32_t addr) {
  asm volatile("ldmatrix.sync.aligned.m8n8.x4.shared.b16 {%0,%1,%2,%3}, [%4];"
      : "=r"(r[0]), "=r"(r[1]), "=r"(r[2]), "=r"(r[3]) : "r"(addr));
}

__device__ __forceinline__ uint32_t packb(__nv_bfloat16 a, __nv_bfloat16 b) {
  __nv_bfloat162 t(a, b);
  return *reinterpret_cast<uint32_t*>(&t);
}

__device__ __forceinline__ void cvt_hilo(float4 v, uint2& hi, uint2& lo) {
  __nv_bfloat16 h0 = __float2bfloat16(v.x), h1 = __float2bfloat16(v.y);
  __nv_bfloat16 h2 = __float2bfloat16(v.z), h3 = __float2bfloat16(v.w);
  hi = make_uint2(packb(h0, h1), packb(h2, h3));
  lo = make_uint2(packb(__float2bfloat16(v.x - __bfloat162float(h0)),
                        __float2bfloat16(v.y - __bfloat162float(h1))),
                  packb(__float2bfloat16(v.z - __bfloat162float(h2)),
                        __float2bfloat16(v.w - __bfloat162float(h3))));
}

// m16n8k16 row.col bf16 -> f32
__device__ __forceinline__ void mma_bf16(float* d, const uint32_t* a,
                                         const uint32_t* b, const float* c) {
  asm volatile(
      "mma.sync.aligned.m16n8k16.row.col.f32.bf16.bf16.f32 "
      "{%0,%1,%2,%3}, {%4,%5,%6,%7}, {%8,%9}, {%10,%11,%12,%13};"
      : "=f"(d[0]), "=f"(d[1]), "=f"(d[2]), "=f"(d[3])
      : "r"(a[0]), "r"(a[1]), "r"(a[2]), "r"(a[3]),
        "r"(b[0]), "r"(b[1]),
        "f"(c[0]), "f"(c[1]), "f"(c[2]), "f"(c[3]));
}

__device__ __forceinline__ void sth(void* p, float v) {
  __nv_bfloat16 h = __float2bfloat16(v);
  *(__nv_bfloat16*)p = h;
}
__device__ __forceinline__ void sth_lo(void* p, float v) {
  __nv_bfloat16 h = __float2bfloat16(v);
  *(__nv_bfloat16*)p = __float2bfloat16(v - __bfloat162float(h));
}

// ---------------------------------------------------------------------------
// prep: proj [256 j][64 d] f32 -> bf16 hi/lo smem-image (swizzled 128B rows)
// group g: row = g>>3, c = g&7 holds elements d = 8*(c^(row&7)) .. +8
__global__ void prep_proj(const float* __restrict__ proj) {
  int g = blockIdx.x * blockDim.x + threadIdx.x;
  if (g >= 2048) return;
  int row = g >> 3, c = g & 7;
  int d0 = 8 * (c ^ (row & 7));
  const float4* p = (const float4*)(proj + row * 64 + d0);
  uint2 h0, l0, h1, l1;
  cvt_hilo(p[0], h0, l0);
  cvt_hilo(p[1], h1, l1);
  g_proj_hi[g] = make_uint4(h0.x, h0.y, h1.x, h1.y);
  g_proj_lo[g] = make_uint4(l0.x, l0.y, l1.x, l1.y);
}

// ---------------------------------------------------------------------------
// Reduce 16 partials -> ctx bf16 smem-image (e<64) + ksum f32 (row 64)
__global__ void reduce_kernel() {
  int idx = blockIdx.x * blockDim.x + threadIdx.x;
  const size_t stride = (size_t)BH_ * 72 * NF_;
  if (idx < BH_ * 64 * 32) {
    int bh = idx >> 11;
    int e  = (idx >> 5) & 63;
    int ch = idx & 31;
    const float* p = g_ctx_part + (size_t)bh * 72 * NF_ + e * NF_ + ch * 8;
    float s[8];
#pragma unroll
    for (int l = 0; l < 8; l++) s[l] = 0.f;
#pragma unroll
    for (int xb = 0; xb < 16; xb++) {
      const float* q = p + xb * stride;
#pragma unroll
      for (int l = 0; l < 8; l++) s[l] += q[l];
    }
    uint2 h0, l0, h1, l1;
    cvt_hilo(make_float4(s[0], s[1], s[2], s[3]), h0, l0);
    cvt_hilo(make_float4(s[4], s[5], s[6], s[7]), h1, l1);
    int swc = (ch & 24) | ((ch ^ e) & 7);
    int gi = bh * 2048 + e * 32 + swc;
    g_ctx_hi[gi] = make_uint4(h0.x, h0.y, h1.x, h1.y);
    g_ctx_lo[gi] = make_uint4(l0.x, l0.y, l1.x, l1.y);
  } else {
    int k = idx - BH_ * 64 * 32;
    if (k < BH_ * NF_) {
      int bh = k >> 8, j = k & 255;
      const float* p = g_ctx_part + (size_t)bh * 72 * NF_ + 64 * NF_ + j;
      float s = 0.f;
#pragma unroll
      for (int xb = 0; xb < 16; xb++) s += p[xb * stride];
      g_ksum[k] = s;
    }
  }
}

// ---------------------------------------------------------------------------
// Fused kernel AB (transposed MMA1): per block 256 tokens of one bh, 4 subtiles.
#define AB_OPHI 0
#define AB_OPLO 32768
#define AB_OKHI 65536
#define AB_OKLO 73728
#define AB_OVHI 81920
#define AB_OVLO 91136
#define AB_ODN  100608
#define AB_OMX  100864
#define SMEMAB  102912

__global__ __launch_bounds__(256, 1)
void kernelAB(const float* __restrict__ kin,
              const float* __restrict__ vin) {
  extern __shared__ char smc[];
  const uint32_t sb = smem_u32(smc);
  float* dn_s  = (float*)(smc + AB_ODN);
  float* mxw_s = (float*)(smc + AB_OMX);   // [8 warps][64 t]

  const int tid  = threadIdx.x;
  const int warp = tid >> 5;
  const int lane = tid & 31;
  const int grp  = lane >> 2;
  const int qd   = lane & 3;
  const int lg   = lane >> 3;
  const int li   = lane & 7;
  const int bh   = blockIdx.y;
  const int tb   = blockIdx.x * 256;

  // --- proj image copy ---
  {
    uint4* dh = (uint4*)(smc + AB_OPHI);
    uint4* dl = (uint4*)(smc + AB_OPLO);
#pragma unroll
    for (int i = tid; i < 2048; i += 256) {
      dh[i] = g_proj_hi[i];
      dl[i] = g_proj_lo[i];
    }
  }
  // --- zero v' rows 65..71 ---
  for (int i = tid; i < 448; i += 256) {
    *(uint16_t*)(smc + AB_OVHI + 65*128 + i*2) = 0;
    *(uint16_t*)(smc + AB_OVLO + 65*128 + i*2) = 0;
  }

  float oacc[2][9][4];
#pragma unroll
  for (int a = 0; a < 2; a++)
#pragma unroll
    for (int b = 0; b < 9; b++)
#pragma unroll
      for (int c = 0; c < 4; c++) oacc[a][b][c] = 0.f;

  const int rq  = tid >> 2;
  const int qtr = tid & 3;

  for (int it = 0; it < 4; it++) {
    const int t0 = tb + it * 64;

    // --- phase 1: k subtile [64 t][64 d] -> smem hi/lo + dn ---
    {
      const float4* kg = (const float4*)(kin + ((size_t)(bh*T_ + t0 + rq)) * DH_);
      float dsum = 0.f;
#pragma unroll
      for (int c = 0; c < 4; c++) {
        float4 v = kg[qtr*4 + c];
        dsum += v.x*v.x + v.y*v.y + v.z*v.z + v.w*v.w;
        int g4 = qtr*4 + c;
        uint32_t off = (uint32_t)rq*128
                     + (uint32_t)((((g4>>1) ^ (rq&7)) << 4)) + (uint32_t)((g4&1)*8);
        uint2 hi, lo; cvt_hilo(v, hi, lo);
        *(uint2*)(smc + AB_OKHI + off) = hi;
        *(uint2*)(smc + AB_OKLO + off) = lo;
      }
      dsum += __shfl_xor_sync(0xffffffff, dsum, 1);
      dsum += __shfl_xor_sync(0xffffffff, dsum, 2);
      if (qtr == 0) dn_s[rq] = dsum;
    }
    __syncthreads();

    // --- phase 2: MMA1 (dpT = proj @ k^T) + exp + qa pack + colmax ---
    uint32_t qa_hi[2][4][4], qa_lo[2][4][4];
#pragma unroll
    for (int mt = 0; mt < 2; mt++) {
      const int j0 = warp * 32 + mt * 16;
      uint32_t ap_hi[4][4], ap_lo[4][4];
#pragma unroll
      for (int kc = 0; kc < 4; kc++) {
        int row = j0 + ((lg & 1) << 3) + li;
        int ch  = kc*2 + (lg >> 1);
        uint32_t off = (uint32_t)row*128 + (uint32_t)(((ch ^ li) & 7) << 4);
        ldmx4(ap_hi[kc], sb + AB_OPHI + off);
        ldmx4(ap_lo[kc], sb + AB_OPLO + off);
      }
#pragma unroll
      for (int ntp = 0; ntp < 4; ntp++) {
        float x0[4] = {0,0,0,0}, y0[4] = {0,0,0,0};
        float x1[4] = {0,0,0,0}, y1[4] = {0,0,0,0};
#pragma unroll
        for (int kc = 0; kc < 4; kc++) {
          int row = ntp*16 + ((lg >> 1) << 3) + li;
          int ch  = kc*2 + (lg & 1);
          uint32_t off = (uint32_t)row*128 + (uint32_t)(((ch ^ li) & 7) << 4);
          uint32_t bh_[4], bl_[4];
          ldmx4(bh_, sb + AB_OKHI + off);
          ldmx4(bl_, sb + AB_OKLO + off);
          mma_bf16(x0, ap_hi[kc], bh_ + 0, x0);
          mma_bf16(y0, ap_lo[kc], bh_ + 0, y0);
          mma_bf16(y0, ap_hi[kc], bl_ + 0, y0);
          mma_bf16(x1, ap_hi[kc], bh_ + 2, x1);
          mma_bf16(y1, ap_lo[kc], bh_ + 2, y1);
          mma_bf16(y1, ap_hi[kc], bl_ + 2, y1);
        }
        float d00 = DS*(x0[0]+y0[0]), d01 = DS*(x0[1]+y0[1]);
        float d02 = DS*(x0[2]+y0[2]), d03 = DS*(x0[3]+y0[3]);
        float d10 = DS*(x1[0]+y1[0]), d11 = DS*(x1[1]+y1[1]);
        float d12 = DS*(x1[2]+y1[2]), d13 = DS*(x1[3]+y1[3]);

        float2 dnA = *(float2*)(dn_s + 16*ntp + 2*qd);
        float2 dnB = *(float2*)(dn_s + 16*ntp + 8 + 2*qd);
        float e00 = __expf(d00 - DNC*dnA.x), e01 = __expf(d01 - DNC*dnA.y);
        float e02 = __expf(d02 - DNC*dnA.x), e03 = __expf(d03 - DNC*dnA.y);
        float e10 = __expf(d10 - DNC*dnB.x), e11 = __expf(d11 - DNC*dnB.y);
        float e12 = __expf(d12 - DNC*dnB.x), e13 = __expf(d13 - DNC*dnB.y);

        float mA0 = fmaxf(d00, d02), mA1 = fmaxf(d01, d03);
        float mB0 = fmaxf(d10, d12), mB1 = fmaxf(d11, d13);
#pragma unroll
        for (int s = 4; s < 32; s <<= 1) {
          mA0 = fmaxf(mA0, __shfl_xor_sync(0xffffffff, mA0, s));
          mA1 = fmaxf(mA1, __shfl_xor_sync(0xffffffff, mA1, s));
          mB0 = fmaxf(mB0, __shfl_xor_sync(0xffffffff, mB0, s));
          mB1 = fmaxf(mB1, __shfl_xor_sync(0xffffffff, mB1, s));
        }
        if (grp == 0) {
          float* mw = mxw_s + warp*64 + 16*ntp + 2*qd;
          if (mt == 0) {
            mw[0] = mA0; mw[1] = mA1; mw[8] = mB0; mw[9] = mB1;
          } else {
            mw[0] = fmaxf(mw[0], mA0); mw[1] = fmaxf(mw[1], mA1);
            mw[8] = fmaxf(mw[8], mB0); mw[9] = fmaxf(mw[9], mB1);
          }
        }

        __nv_bfloat16 h00 = __float2bfloat16(e00), h01 = __float2bfloat16(e01);
        __nv_bfloat16 h02 = __float2bfloat16(e02), h03 = __float2bfloat16(e03);
        __nv_bfloat16 h10 = __float2bfloat16(e10), h11 = __float2bfloat16(e11);
        __nv_bfloat16 h12 = __float2bfloat16(e12), h13 = __float2bfloat16(e13);
        qa_hi[mt][ntp][0] = packb(h00, h01);
        qa_hi[mt][ntp][1] = packb(h02, h03);
        qa_hi[mt][ntp][2] = packb(h10, h11);
        qa_hi[mt][ntp][3] = packb(h12, h13);
        qa_lo[mt][ntp][0] = packb(__float2bfloat16(e00 - __bfloat162float(h00)),
                                  __float2bfloat16(e01 - __bfloat162float(h01)));
        qa_lo[mt][ntp][1] = packb(__float2bfloat16(e02 - __bfloat162float(h02)),
                                  __float2bfloat16(e03 - __bfloat162float(h03)));
        qa_lo[mt][ntp][2] = packb(__float2bfloat16(e10 - __bfloat162float(h10)),
                                  __float2bfloat16(e11 - __bfloat162float(h11)));
        qa_lo[mt][ntp][3] = packb(__float2bfloat16(e12 - __bfloat162float(h12)),
                                  __float2bfloat16(e13 - __bfloat162float(h13)));
      }
    }
    __syncthreads();

    // --- phase 4: v' = w*v transposed to vT[e][t]; w column at e=64 ---
    {
      float m = mxw_s[rq];
#pragma unroll
      for (int w = 1; w < 8; w++) m = fmaxf(m, mxw_s[w*64 + rq]);
      float wv = __expf(-m);
      const float4* vg = (const float4*)(vin + ((size_t)(bh*T_ + t0 + rq)) * DH_);
#pragma unroll
      for (int c = 0; c < 4; c++) {
        float4 v = vg[qtr*4 + c];
        v.x *= wv; v.y *= wv; v.z *= wv; v.w *= wv;
        int e0 = qtr*16 + c*4;
        float vv[4] = {v.x, v.y, v.z, v.w};
#pragma unroll
        for (int l = 0; l < 4; l++) {
          int e = e0 + l;
          uint32_t off = (uint32_t)e*128 + ((((rq>>3) ^ (e&7))<<4)) + (rq&7)*2;
          sth(smc + AB_OVHI + off, vv[l]);
          sth_lo(smc + AB_OVLO + off, vv[l]);
        }
      }
      if (tid < 64) {
        float m2 = mxw_s[tid];
#pragma unroll
        for (int w = 1; w < 8; w++) m2 = fmaxf(m2, mxw_s[w*64 + tid]);
        float w2 = __expf(-m2);
        uint32_t off = (uint32_t)64*128 + (((tid>>3))<<4) + (tid&7)*2;
        sth(smc + AB_OVHI + off, w2);
        sth_lo(smc + AB_OVLO + off, w2);
      }
    }
    __syncthreads();

    // --- phase 5: MMA2: oacc += sT @ v' (A = qa registers) ---
#pragma unroll
    for (int kc = 0; kc < 4; kc++) {
#pragma unroll
      for (int ntp = 0; ntp < 4; ntp++) {
        uint32_t bvh[4], bvl[4];
        int row = ntp*16 + ((lg >> 1) << 3) + li;
        int ch  = kc*2 + (lg & 1);
        uint32_t off = (uint32_t)row*128 + (uint32_t)(((ch ^ li) & 7) << 4);
        ldmx4(bvh, sb + AB_OVHI + off);
        ldmx4(bvl, sb + AB_OVLO + off);
#pragma unroll
        for (int mt = 0; mt < 2; mt++) {
          int nt0 = ntp*2, nt1 = ntp*2 + 1;
          mma_bf16(oacc[mt][nt0], qa_hi[mt][kc], bvh + 0, oacc[mt][nt0]);
          mma_bf16(oacc[mt][nt0], qa_lo[mt][kc], bvh + 0, oacc[mt][nt0]);
          mma_bf16(oacc[mt][nt0], qa_hi[mt][kc], bvl + 0, oacc[mt][nt0]);
          mma_bf16(oacc[mt][nt1], qa_hi[mt][kc], bvh + 2, oacc[mt][nt1]);
          mma_bf16(oacc[mt][nt1], qa_lo[mt][kc], bvh + 2, oacc[mt][nt1]);
          mma_bf16(oacc[mt][nt1], qa_hi[mt][kc], bvl + 2, oacc[mt][nt1]);
        }
      }
      // nt = 8 (e rows 64..71, scalar B loads)
      {
        uint32_t c0 = (uint32_t)(((kc*2)     ^ grp) << 4);
        uint32_t c1 = (uint32_t)(((kc*2 + 1) ^ grp) << 4);
        uint32_t rb = (uint32_t)(64 + grp) * 128u + (uint32_t)(qd * 4);
        uint32_t bvh[2] = { *(uint32_t*)(smc + AB_OVHI + rb + c0),
                            *(uint32_t*)(smc + AB_OVHI + rb + c1) };
        uint32_t bvl[2] = { *(uint32_t*)(smc + AB_OVLO + rb + c0),
                            *(uint32_t*)(smc + AB_OVLO + rb + c1) };
#pragma unroll
        for (int mt = 0; mt < 2; mt++) {
          mma_bf16(oacc[mt][8], qa_hi[mt][kc], bvh, oacc[mt][8]);
          mma_bf16(oacc[mt][8], qa_lo[mt][kc], bvh, oacc[mt][8]);
          mma_bf16(oacc[mt][8], qa_hi[mt][kc], bvl, oacc[mt][8]);
        }
      }
    }
    __syncthreads();   // v'/k_s consumed before next subtile overwrites
  }

  // --- final: store partial to g_ctx_part[xb][bh][e][j] ---
  float* ctxp = g_ctx_part + ((size_t)blockIdx.x * BH_ + bh) * 72 * NF_;
#pragma unroll
  for (int mt = 0; mt < 2; mt++)
#pragma unroll
    for (int nt = 0; nt < 9; nt++)
#pragma unroll
      for (int c = 0; c < 4; c++) {
        int j = warp*32 + mt*16 + grp + ((c >= 2) ? 8 : 0);
        int e = nt*8 + qd*2 + (c & 1);
        if (e < 65) ctxp[e * NF_ + j] = oacc[mt][nt][c];
      }
}

// ---------------------------------------------------------------------------
// Kernel C: image copies + x/y/z split MMA1
#define OQHI  0
#define OQLO  16384
#define OPHI  32768
#define OPLO  65536
#define OCHI  98304
#define OCLO  131072
#define OKS   163840
#define ODN   164864
#define SMEMC 165504

__global__ __launch_bounds__(256, 1)
void kernelC(const float* __restrict__ qin,
             float* __restrict__ outg) {
  extern __shared__ char smc[];
  const uint32_t sb = smem_u32(smc);
  float* ks_s = (float*)(smc + OKS);
  float* dn_s = (float*)(smc + ODN);

  const int tid  = threadIdx.x;
  const int warp = tid >> 5;
  const int lane = tid & 31;
  const int grp  = lane >> 2;
  const int qd   = lane & 3;
  const int lg   = lane >> 3;
  const int li   = lane & 7;
  const int bh   = blockIdx.y;
  const int t0   = blockIdx.x * 128;

  // --- image copies: proj + ctx ---
  {
    uint4* ph = (uint4*)(smc + OPHI);
    uint4* pl = (uint4*)(smc + OPLO);
    uint4* ch_ = (uint4*)(smc + OCHI);
    uint4* cl_ = (uint4*)(smc + OCLO);
    const uint4* gh = g_ctx_hi + bh * 2048;
    const uint4* gl = g_ctx_lo + bh * 2048;
#pragma unroll
    for (int i = tid; i < 2048; i += 256) {
      ph[i] = g_proj_hi[i];
      pl[i] = g_proj_lo[i];
      ch_[i] = gh[i];
      cl_[i] = gl[i];
    }
  }
  // --- q [128][64] -> bf16 hi/lo + per-row |q|^2 ---
  {
    const int rq = tid >> 1, half = tid & 1;
    const float4* qg = (const float4*)(qin + ((size_t)(bh * T_ + t0 + rq)) * DH_);
    float dsum = 0.f;
#pragma unroll
    for (int c = 0; c < 8; c++) {
      float4 v = qg[half*8 + c];
      dsum += v.x*v.x + v.y*v.y + v.z*v.z + v.w*v.w;
      int kp = half*32 + c*4;
      uint32_t off = (uint32_t)rq*128 + (uint32_t)(((kp>>3) ^ (rq&7)) << 4)
                   + (uint32_t)((kp&7)*2);
      uint2 hi, lo; cvt_hilo(v, hi, lo);
      *(uint2*)(smc + OQHI + off) = hi;
      *(uint2*)(smc + OQLO + off) = lo;
    }
    dsum += __shfl_xor_sync(0xffffffff, dsum, 1);
    if (half == 0) dn_s[rq] = dsum;
  }
  ks_s[tid] = g_ksum[bh * NF_ + tid];
  ks_s[tid + 128] = g_ksum[bh * NF_ + tid + 128];
  __syncthreads();

  const int r0 = warp * 16;
  uint32_t aq_hi[4][4], aq_lo[4][4];
#pragma unroll
  for (int kc = 0; kc < 4; kc++) {
    int row = r0 + ((lg & 1) << 3) + li;
    int ch  = kc*2 + (lg >> 1);
    uint32_t off = (uint32_t)row*128 + (uint32_t)(((ch ^ li) & 7) << 4);
    ldmx4(aq_hi[kc], sb + OQHI + off);
    ldmx4(aq_lo[kc], sb + OQLO + off);
  }

  float oacc[8][4];
#pragma unroll
  for (int et = 0; et < 8; et++)
#pragma unroll
    for (int i = 0; i < 4; i++) oacc[et][i] = 0.f;

  float den0 = 0.f, den1 = 0.f;
  const float dnt0 = DNC * dn_s[r0 + grp];
  const float dnt1 = DNC * dn_s[r0 + grp + 8];

  for (int jt = 0; jt < 16; jt++) {
    const int j0 = jt * 16;
    float x0[4] = {0,0,0,0}, y0[4] = {0,0,0,0}, z0[4] = {0,0,0,0};
    float x1[4] = {0,0,0,0}, y1[4] = {0,0,0,0}, z1[4] = {0,0,0,0};
#pragma unroll
    for (int kc = 0; kc < 4; kc++) {
      int row = j0 + ((lg >> 1) << 3) + li;
      int ch  = kc*2 + (lg & 1);
      uint32_t off = (uint32_t)row*128 + (uint32_t)(((ch ^ li) & 7) << 4);
      uint32_t bh_[4], bl_[4];
      ldmx4(bh_, sb + OPHI + off);
      ldmx4(bl_, sb + OPLO + off);
      mma_bf16(x0, aq_hi[kc], bh_ + 0, x0);
      mma_bf16(y0, aq_lo[kc], bh_ + 0, y0);
      mma_bf16(z0, aq_hi[kc], bl_ + 0, z0);
      mma_bf16(x1, aq_hi[kc], bh_ + 2, x1);
      mma_bf16(y1, aq_lo[kc], bh_ + 2, y1);
      mma_bf16(z1, aq_hi[kc], bl_ + 2, z1);
    }

    float e00 = __expf(fmaf(DS, x0[0] + (y0[0] + z0[0]), -dnt0));
    float e01 = __expf(fmaf(DS, x0[1] + (y0[1] + z0[1]), -dnt0));
    float e02 = __expf(fmaf(DS, x0[2] + (y0[2] + z0[2]), -dnt1));
    float e03 = __expf(fmaf(DS, x0[3] + (y0[3] + z0[3]), -dnt1));
    float e10 = __expf(fmaf(DS, x1[0] + (y1[0] + z1[0]), -dnt0));
    float e11 = __expf(fmaf(DS, x1[1] + (y1[1] + z1[1]), -dnt0));
    float e12 = __expf(fmaf(DS, x1[2] + (y1[2] + z1[2]), -dnt1));
    float e13 = __expf(fmaf(DS, x1[3] + (y1[3] + z1[3]), -dnt1));

    float2 kv0 = *(float2*)(ks_s + j0 + qd*2);
    float2 kv1 = *(float2*)(ks_s + j0 + 8 + qd*2);
    den0 = fmaf(e00, kv0.x, fmaf(e01, kv0.y, fmaf(e10, kv1.x, fmaf(e11, kv1.y, den0))));
    den1 = fmaf(e02, kv0.x, fmaf(e03, kv0.y, fmaf(e12, kv1.x, fmaf(e13, kv1.y, den1))));

    __nv_bfloat16 h00 = __float2bfloat16(e00), h01 = __float2bfloat16(e01);
    __nv_bfloat16 h02 = __float2bfloat16(e02), h03 = __float2bfloat16(e03);
    __nv_bfloat16 h10 = __float2bfloat16(e10), h11 = __float2bfloat16(e11);
    __nv_bfloat16 h12 = __float2bfloat16(e12), h13 = __float2bfloat16(e13);
    uint32_t qa_hi[4] = { packb(h00, h01), packb(h02, h03),
                          packb(h10, h11), packb(h12, h13) };
    uint32_t qa_lo[4] = {
      packb(__float2bfloat16(e00 - __bfloat162float(h00)),
            __float2bfloat16(e01 - __bfloat162float(h01))),
      packb(__float2bfloat16(e02 - __bfloat162float(h02)),
            __float2bfloat16(e03 - __bfloat162float(h03))),
      packb(__float2bfloat16(e10 - __bfloat162float(h10)),
            __float2bfloat16(e11 - __bfloat162float(h11))),
      packb(__float2bfloat16(e12 - __bfloat162float(h12)),
            __float2bfloat16(e13 - __bfloat162float(h13))) };

    const int ch0 = jt * 2;
#pragma unroll
    for (int etp = 0; etp < 4; etp++) {
      uint32_t bh_[4], bl_[4];
      int e = (etp*2 + (lg >> 1))*8 + li;
      int ch = ch0 + (lg & 1);
      uint32_t off = (uint32_t)e*512
                   + (uint32_t)((((ch & 24) | ((ch ^ li) & 7))) << 4);
      ldmx4(bh_, sb + OCHI + off);
      ldmx4(bl_, sb + OCLO + off);
      int et0 = etp*2, et1 = etp*2 + 1;
      mma_bf16(oacc[et0], qa_hi, bh_ + 0, oacc[et0]);
      mma_bf16(oacc[et0], qa_lo, bh_ + 0, oacc[et0]);
      mma_bf16(oacc[et0], qa_hi, bl_ + 0, oacc[et0]);
      mma_bf16(oacc[et1], qa_hi, bh_ + 2, oacc[et1]);
      mma_bf16(oacc[et1], qa_lo, bh_ + 2, oacc[et1]);
      mma_bf16(oacc[et1], qa_hi, bl_ + 2, oacc[et1]);
    }
  }

  den0 += __shfl_xor_sync(0xffffffff, den0, 1);
  den0 += __shfl_xor_sync(0xffffffff, den0, 2);
  den1 += __shfl_xor_sync(0xffffffff, den1, 1);
  den1 += __shfl_xor_sync(0xffffffff, den1, 2);
  float inv0 = 1.f / den0, inv1 = 1.f / den1;

  float* og0 = outg + ((size_t)(bh * T_ + t0 + r0 + grp)) * DH_;
  float* og1 = og0 + 8 * DH_;
#pragma unroll
  for (int et = 0; et < 8; et++) {
    int col = et * 8 + qd * 2;
    *(float2*)(og0 + col) = make_float2(oacc[et][0] * inv0, oacc[et][1] * inv0);
    *(float2*)(og1 + col) = make_float2(oacc[et][2] * inv1, oacc[et][3] * inv1);
  }
}

// ---------------------------------------------------------------------------
extern "C" void kernel_launch(void* const* d_in, const int* in_sizes, int n_in,
                              void* d_out, int out_size) {
  const float* q    = (const float*)d_in[0];
  const float* k    = (const float*)d_in[1];
  const float* v    = (const float*)d_in[2];
  const float* proj = (const float*)d_in[3];
  float* out = (float*)d_out;

  cudaFuncSetAttribute(kernelAB, cudaFuncAttributeMaxDynamicSharedMemorySize, SMEMAB);
  cudaFuncSetAttribute(kernelC,  cudaFuncAttributeMaxDynamicSharedMemorySize, SMEMC);

  prep_proj<<<8, 256>>>(proj);
  kernelAB<<<dim3(16, BH_), 256, SMEMAB>>>(k, v);
  reduce_kernel<<<576, 256>>>();
  kernelC<<<dim3(T_/128, BH_), 256, SMEMC>>>(q, out);
}

// round 17
// speedup vs baseline: 1.0531x; 1.0531x over previous
#include <cuda_runtime.h>
#include <cuda_bf16.h>
#include <math.h>
#include <cstdint>

#define T_  4096
#define NF_ 256
#define DH_ 64
#define BH_ 64
#define DS  0.35355339059327373f
#define DNC 0.0625f

// per-xb partial ctx: [xb=16][bh][e'=72][j=256] (only e<65 written/read)
__device__ float g_ctx_part[16 * BH_ * 72 * NF_];
// precomputed bf16 smem-images
__device__ uint4 g_proj_hi[2048], g_proj_lo[2048];            // 32KB each
__device__ uint4 g_ctx_hi[BH_ * 2048], g_ctx_lo[BH_ * 2048];  // 32KB per bh
__device__ float g_ksum[BH_ * NF_];

__device__ __forceinline__ uint32_t smem_u32(const void* p) {
  uint32_t a;
  asm("{ .reg .u64 tmp; cvta.to.shared.u64 tmp, %1; cvt.u32.u64 %0, tmp; }"
      : "=r"(a) : "l"(p));
  return a;
}

__device__ __forceinline__ void ldmx4(uint32_t* r, uint32_t addr) {
  asm volatile("ldmatrix.sync.aligned.m8n8.x4.shared.b16 {%0,%1,%2,%3}, [%4];"
      : "=r"(r[0]), "=r"(r[1]), "=r"(r[2]), "=r"(r[3]) : "r"(addr));
}

__device__ __forceinline__ uint32_t packb(__nv_bfloat16 a, __nv_bfloat16 b) {
  __nv_bfloat162 t(a, b);
  return *reinterpret_cast<uint32_t*>(&t);
}

__device__ __forceinline__ void cvt_hilo(float4 v, uint2& hi, uint2& lo) {
  __nv_bfloat16 h0 = __float2bfloat16(v.x), h1 = __float2bfloat16(v.y);
  __nv_bfloat16 h2 = __float2bfloat16(v.z), h3 = __float2bfloat16(v.w);
  hi = make_uint2(packb(h0, h1), packb(h2, h3));
  lo = make_uint2(packb(__float2bfloat16(v.x - __bfloat162float(h0)),
                        __float2bfloat16(v.y - __bfloat162float(h1))),
                  packb(__float2bfloat16(v.z - __bfloat162float(h2)),
                        __float2bfloat16(v.w - __bfloat162float(h3))));
}

// m16n8k16 row.col bf16 -> f32
__device__ __forceinline__ void mma_bf16(float* d, const uint32_t* a,
                                         const uint32_t* b, const float* c) {
  asm volatile(
      "mma.sync.aligned.m16n8k16.row.col.f32.bf16.bf16.f32 "
      "{%0,%1,%2,%3}, {%4,%5,%6,%7}, {%8,%9}, {%10,%11,%12,%13};"
      : "=f"(d[0]), "=f"(d[1]), "=f"(d[2]), "=f"(d[3])
      : "r"(a[0]), "r"(a[1]), "r"(a[2]), "r"(a[3]),
        "r"(b[0]), "r"(b[1]),
        "f"(c[0]), "f"(c[1]), "f"(c[2]), "f"(c[3]));
}

__device__ __forceinline__ void sth(void* p, float v) {
  __nv_bfloat16 h = __float2bfloat16(v);
  *(__nv_bfloat16*)p = h;
}
__device__ __forceinline__ void sth_lo(void* p, float v) {
  __nv_bfloat16 h = __float2bfloat16(v);
  *(__nv_bfloat16*)p = __float2bfloat16(v - __bfloat162float(h));
}

// ---------------------------------------------------------------------------
// prep: proj [256 j][64 d] f32 -> bf16 hi/lo smem-image (swizzled 128B rows)
__global__ void prep_proj(const float* __restrict__ proj) {
  int g = blockIdx.x * blockDim.x + threadIdx.x;
  if (g >= 2048) return;
  int row = g >> 3, c = g & 7;
  int d0 = 8 * (c ^ (row & 7));
  const float4* p = (const float4*)(proj + row * 64 + d0);
  uint2 h0, l0, h1, l1;
  cvt_hilo(p[0], h0, l0);
  cvt_hilo(p[1], h1, l1);
  g_proj_hi[g] = make_uint4(h0.x, h0.y, h1.x, h1.y);
  g_proj_lo[g] = make_uint4(l0.x, l0.y, l1.x, l1.y);
}

// ---------------------------------------------------------------------------
// Reduce 16 partials -> ctx bf16 smem-image (e<64) + ksum f32 (row 64)
__global__ void reduce_kernel() {
  int idx = blockIdx.x * blockDim.x + threadIdx.x;
  const size_t stride = (size_t)BH_ * 72 * NF_;
  if (idx < BH_ * 64 * 32) {
    int bh = idx >> 11;
    int e  = (idx >> 5) & 63;
    int ch = idx & 31;
    const float* p = g_ctx_part + (size_t)bh * 72 * NF_ + e * NF_ + ch * 8;
    float s[8];
#pragma unroll
    for (int l = 0; l < 8; l++) s[l] = 0.f;
#pragma unroll
    for (int xb = 0; xb < 16; xb++) {
      const float* q = p + xb * stride;
#pragma unroll
      for (int l = 0; l < 8; l++) s[l] += q[l];
    }
    uint2 h0, l0, h1, l1;
    cvt_hilo(make_float4(s[0], s[1], s[2], s[3]), h0, l0);
    cvt_hilo(make_float4(s[4], s[5], s[6], s[7]), h1, l1);
    int swc = (ch & 24) | ((ch ^ e) & 7);
    int gi = bh * 2048 + e * 32 + swc;
    g_ctx_hi[gi] = make_uint4(h0.x, h0.y, h1.x, h1.y);
    g_ctx_lo[gi] = make_uint4(l0.x, l0.y, l1.x, l1.y);
  } else {
    int k = idx - BH_ * 64 * 32;
    if (k < BH_ * NF_) {
      int bh = k >> 8, j = k & 255;
      const float* p = g_ctx_part + (size_t)bh * 72 * NF_ + 64 * NF_ + j;
      float s = 0.f;
#pragma unroll
      for (int xb = 0; xb < 16; xb++) s += p[xb * stride];
      g_ksum[k] = s;
    }
  }
}

// ---------------------------------------------------------------------------
// Fused kernel AB (transposed MMA1): per block 256 tokens of one bh, 4 subtiles.
#define AB_OPHI 0
#define AB_OPLO 32768
#define AB_OKHI 65536
#define AB_OKLO 73728
#define AB_OVHI 81920
#define AB_OVLO 91136
#define AB_ODN  100608
#define AB_OMX  100864
#define SMEMAB  102912

__global__ __launch_bounds__(256, 1)
void kernelAB(const float* __restrict__ kin,
              const float* __restrict__ vin) {
  extern __shared__ char smc[];
  const uint32_t sb = smem_u32(smc);
  float* dn_s  = (float*)(smc + AB_ODN);
  float* mxw_s = (float*)(smc + AB_OMX);   // [8 warps][64 t]

  const int tid  = threadIdx.x;
  const int warp = tid >> 5;
  const int lane = tid & 31;
  const int grp  = lane >> 2;
  const int qd   = lane & 3;
  const int lg   = lane >> 3;
  const int li   = lane & 7;
  const int bh   = blockIdx.y;
  const int tb   = blockIdx.x * 256;

  // --- proj image copy ---
  {
    uint4* dh = (uint4*)(smc + AB_OPHI);
    uint4* dl = (uint4*)(smc + AB_OPLO);
#pragma unroll
    for (int i = tid; i < 2048; i += 256) {
      dh[i] = g_proj_hi[i];
      dl[i] = g_proj_lo[i];
    }
  }
  // --- zero v' rows 65..71 ---
  for (int i = tid; i < 448; i += 256) {
    *(uint16_t*)(smc + AB_OVHI + 65*128 + i*2) = 0;
    *(uint16_t*)(smc + AB_OVLO + 65*128 + i*2) = 0;
  }

  float oacc[2][9][4];
#pragma unroll
  for (int a = 0; a < 2; a++)
#pragma unroll
    for (int b = 0; b < 9; b++)
#pragma unroll
      for (int c = 0; c < 4; c++) oacc[a][b][c] = 0.f;

  const int rq  = tid >> 2;
  const int qtr = tid & 3;

  for (int it = 0; it < 4; it++) {
    const int t0 = tb + it * 64;

    // --- phase 1: k subtile [64 t][64 d] -> smem hi/lo + dn ---
    {
      const float4* kg = (const float4*)(kin + ((size_t)(bh*T_ + t0 + rq)) * DH_);
      float dsum = 0.f;
#pragma unroll
      for (int c = 0; c < 4; c++) {
        float4 v = kg[qtr*4 + c];
        dsum += v.x*v.x + v.y*v.y + v.z*v.z + v.w*v.w;
        int g4 = qtr*4 + c;
        uint32_t off = (uint32_t)rq*128
                     + (uint32_t)((((g4>>1) ^ (rq&7)) << 4)) + (uint32_t)((g4&1)*8);
        uint2 hi, lo; cvt_hilo(v, hi, lo);
        *(uint2*)(smc + AB_OKHI + off) = hi;
        *(uint2*)(smc + AB_OKLO + off) = lo;
      }
      dsum += __shfl_xor_sync(0xffffffff, dsum, 1);
      dsum += __shfl_xor_sync(0xffffffff, dsum, 2);
      if (qtr == 0) dn_s[rq] = dsum;
    }
    __syncthreads();

    // --- phase 2: MMA1 (dpT = proj @ k^T) + exp + qa pack + colmax ---
    uint32_t qa_hi[2][4][4], qa_lo[2][4][4];
#pragma unroll
    for (int mt = 0; mt < 2; mt++) {
      const int j0 = warp * 32 + mt * 16;
      uint32_t ap_hi[4][4], ap_lo[4][4];
#pragma unroll
      for (int kc = 0; kc < 4; kc++) {
        int row = j0 + ((lg & 1) << 3) + li;
        int ch  = kc*2 + (lg >> 1);
        uint32_t off = (uint32_t)row*128 + (uint32_t)(((ch ^ li) & 7) << 4);
        ldmx4(ap_hi[kc], sb + AB_OPHI + off);
        ldmx4(ap_lo[kc], sb + AB_OPLO + off);
      }
#pragma unroll
      for (int ntp = 0; ntp < 4; ntp++) {
        float x0[4] = {0,0,0,0}, y0[4] = {0,0,0,0};
        float x1[4] = {0,0,0,0}, y1[4] = {0,0,0,0};
#pragma unroll
        for (int kc = 0; kc < 4; kc++) {
          int row = ntp*16 + ((lg >> 1) << 3) + li;
          int ch  = kc*2 + (lg & 1);
          uint32_t off = (uint32_t)row*128 + (uint32_t)(((ch ^ li) & 7) << 4);
          uint32_t bh_[4], bl_[4];
          ldmx4(bh_, sb + AB_OKHI + off);
          ldmx4(bl_, sb + AB_OKLO + off);
          mma_bf16(x0, ap_hi[kc], bh_ + 0, x0);
          mma_bf16(y0, ap_lo[kc], bh_ + 0, y0);
          mma_bf16(y0, ap_hi[kc], bl_ + 0, y0);
          mma_bf16(x1, ap_hi[kc], bh_ + 2, x1);
          mma_bf16(y1, ap_lo[kc], bh_ + 2, y1);
          mma_bf16(y1, ap_hi[kc], bl_ + 2, y1);
        }
        float d00 = DS*(x0[0]+y0[0]), d01 = DS*(x0[1]+y0[1]);
        float d02 = DS*(x0[2]+y0[2]), d03 = DS*(x0[3]+y0[3]);
        float d10 = DS*(x1[0]+y1[0]), d11 = DS*(x1[1]+y1[1]);
        float d12 = DS*(x1[2]+y1[2]), d13 = DS*(x1[3]+y1[3]);

        float2 dnA = *(float2*)(dn_s + 16*ntp + 2*qd);
        float2 dnB = *(float2*)(dn_s + 16*ntp + 8 + 2*qd);
        float e00 = __expf(d00 - DNC*dnA.x), e01 = __expf(d01 - DNC*dnA.y);
        float e02 = __expf(d02 - DNC*dnA.x), e03 = __expf(d03 - DNC*dnA.y);
        float e10 = __expf(d10 - DNC*dnB.x), e11 = __expf(d11 - DNC*dnB.y);
        float e12 = __expf(d12 - DNC*dnB.x), e13 = __expf(d13 - DNC*dnB.y);

        float mA0 = fmaxf(d00, d02), mA1 = fmaxf(d01, d03);
        float mB0 = fmaxf(d10, d12), mB1 = fmaxf(d11, d13);
#pragma unroll
        for (int s = 4; s < 32; s <<= 1) {
          mA0 = fmaxf(mA0, __shfl_xor_sync(0xffffffff, mA0, s));
          mA1 = fmaxf(mA1, __shfl_xor_sync(0xffffffff, mA1, s));
          mB0 = fmaxf(mB0, __shfl_xor_sync(0xffffffff, mB0, s));
          mB1 = fmaxf(mB1, __shfl_xor_sync(0xffffffff, mB1, s));
        }
        if (grp == 0) {
          float* mw = mxw_s + warp*64 + 16*ntp + 2*qd;
          if (mt == 0) {
            mw[0] = mA0; mw[1] = mA1; mw[8] = mB0; mw[9] = mB1;
          } else {
            mw[0] = fmaxf(mw[0], mA0); mw[1] = fmaxf(mw[1], mA1);
            mw[8] = fmaxf(mw[8], mB0); mw[9] = fmaxf(mw[9], mB1);
          }
        }

        __nv_bfloat16 h00 = __float2bfloat16(e00), h01 = __float2bfloat16(e01);
        __nv_bfloat16 h02 = __float2bfloat16(e02), h03 = __float2bfloat16(e03);
        __nv_bfloat16 h10 = __float2bfloat16(e10), h11 = __float2bfloat16(e11);
        __nv_bfloat16 h12 = __float2bfloat16(e12), h13 = __float2bfloat16(e13);
        qa_hi[mt][ntp][0] = packb(h00, h01);
        qa_hi[mt][ntp][1] = packb(h02, h03);
        qa_hi[mt][ntp][2] = packb(h10, h11);
        qa_hi[mt][ntp][3] = packb(h12, h13);
        qa_lo[mt][ntp][0] = packb(__float2bfloat16(e00 - __bfloat162float(h00)),
                                  __float2bfloat16(e01 - __bfloat162float(h01)));
        qa_lo[mt][ntp][1] = packb(__float2bfloat16(e02 - __bfloat162float(h02)),
                                  __float2bfloat16(e03 - __bfloat162float(h03)));
        qa_lo[mt][ntp][2] = packb(__float2bfloat16(e10 - __bfloat162float(h10)),
                                  __float2bfloat16(e11 - __bfloat162float(h11)));
        qa_lo[mt][ntp][3] = packb(__float2bfloat16(e12 - __bfloat162float(h12)),
                                  __float2bfloat16(e13 - __bfloat162float(h13)));
      }
    }
    __syncthreads();

    // --- phase 4: v' = w*v transposed to vT[e][t]; w column at e=64 ---
    {
      float m = mxw_s[rq];
#pragma unroll
      for (int w = 1; w < 8; w++) m = fmaxf(m, mxw_s[w*64 + rq]);
      float wv = __expf(-m);
      const float4* vg = (const float4*)(vin + ((size_t)(bh*T_ + t0 + rq)) * DH_);
#pragma unroll
      for (int c = 0; c < 4; c++) {
        float4 v = vg[qtr*4 + c];
        v.x *= wv; v.y *= wv; v.z *= wv; v.w *= wv;
        int e0 = qtr*16 + c*4;
        float vv[4] = {v.x, v.y, v.z, v.w};
#pragma unroll
        for (int l = 0; l < 4; l++) {
          int e = e0 + l;
          uint32_t off = (uint32_t)e*128 + ((((rq>>3) ^ (e&7))<<4)) + (rq&7)*2;
          sth(smc + AB_OVHI + off, vv[l]);
          sth_lo(smc + AB_OVLO + off, vv[l]);
        }
      }
      if (tid < 64) {
        float m2 = mxw_s[tid];
#pragma unroll
        for (int w = 1; w < 8; w++) m2 = fmaxf(m2, mxw_s[w*64 + tid]);
        float w2 = __expf(-m2);
        uint32_t off = (uint32_t)64*128 + (((tid>>3))<<4) + (tid&7)*2;
        sth(smc + AB_OVHI + off, w2);
        sth_lo(smc + AB_OVLO + off, w2);
      }
    }
    __syncthreads();

    // --- phase 5: MMA2: oacc += sT @ v' (A = qa registers) ---
#pragma unroll
    for (int kc = 0; kc < 4; kc++) {
#pragma unroll
      for (int ntp = 0; ntp < 4; ntp++) {
        uint32_t bvh[4], bvl[4];
        int row = ntp*16 + ((lg >> 1) << 3) + li;
        int ch  = kc*2 + (lg & 1);
        uint32_t off = (uint32_t)row*128 + (uint32_t)(((ch ^ li) & 7) << 4);
        ldmx4(bvh, sb + AB_OVHI + off);
        ldmx4(bvl, sb + AB_OVLO + off);
#pragma unroll
        for (int mt = 0; mt < 2; mt++) {
          int nt0 = ntp*2, nt1 = ntp*2 + 1;
          mma_bf16(oacc[mt][nt0], qa_hi[mt][kc], bvh + 0, oacc[mt][nt0]);
          mma_bf16(oacc[mt][nt0], qa_lo[mt][kc], bvh + 0, oacc[mt][nt0]);
          mma_bf16(oacc[mt][nt0], qa_hi[mt][kc], bvl + 0, oacc[mt][nt0]);
          mma_bf16(oacc[mt][nt1], qa_hi[mt][kc], bvh + 2, oacc[mt][nt1]);
          mma_bf16(oacc[mt][nt1], qa_lo[mt][kc], bvh + 2, oacc[mt][nt1]);
          mma_bf16(oacc[mt][nt1], qa_hi[mt][kc], bvl + 2, oacc[mt][nt1]);
        }
      }
      // nt = 8 (e rows 64..71, scalar B loads)
      {
        uint32_t c0 = (uint32_t)(((kc*2)     ^ grp) << 4);
        uint32_t c1 = (uint32_t)(((kc*2 + 1) ^ grp) << 4);
        uint32_t rb = (uint32_t)(64 + grp) * 128u + (uint32_t)(qd * 4);
        uint32_t bvh[2] = { *(uint32_t*)(smc + AB_OVHI + rb + c0),
                            *(uint32_t*)(smc + AB_OVHI + rb + c1) };
        uint32_t bvl[2] = { *(uint32_t*)(smc + AB_OVLO + rb + c0),
                            *(uint32_t*)(smc + AB_OVLO + rb + c1) };
#pragma unroll
        for (int mt = 0; mt < 2; mt++) {
          mma_bf16(oacc[mt][8], qa_hi[mt][kc], bvh, oacc[mt][8]);
          mma_bf16(oacc[mt][8], qa_lo[mt][kc], bvh, oacc[mt][8]);
          mma_bf16(oacc[mt][8], qa_hi[mt][kc], bvl, oacc[mt][8]);
        }
      }
    }
    __syncthreads();   // v'/k_s consumed before next subtile overwrites
  }

  // --- final: store partial to g_ctx_part[xb][bh][e][j] ---
  float* ctxp = g_ctx_part + ((size_t)blockIdx.x * BH_ + bh) * 72 * NF_;
#pragma unroll
  for (int mt = 0; mt < 2; mt++)
#pragma unroll
    for (int nt = 0; nt < 9; nt++)
#pragma unroll
      for (int c = 0; c < 4; c++) {
        int j = warp*32 + mt*16 + grp + ((c >= 2) ? 8 : 0);
        int e = nt*8 + qd*2 + (c & 1);
        if (e < 65) ctxp[e * NF_ + j] = oacc[mt][nt][c];
      }
}

// ---------------------------------------------------------------------------
// Kernel C: 256 tokens/block (2 halves), images copied once per block.
#define OQHI  0
#define OQLO  16384
#define OPHI  32768
#define OPLO  65536
#define OCHI  98304
#define OCLO  131072
#define OKS   163840
#define ODN   164864
#define SMEMC 165504

__global__ __launch_bounds__(256, 1)
void kernelC(const float* __restrict__ qin,
             float* __restrict__ outg) {
  extern __shared__ char smc[];
  const uint32_t sb = smem_u32(smc);
  float* ks_s = (float*)(smc + OKS);
  float* dn_s = (float*)(smc + ODN);

  const int tid  = threadIdx.x;
  const int warp = tid >> 5;
  const int lane = tid & 31;
  const int grp  = lane >> 2;
  const int qd   = lane & 3;
  const int lg   = lane >> 3;
  const int li   = lane & 7;
  const int bh   = blockIdx.y;

  // --- image copies: proj + ctx (once per 256 tokens) ---
  {
    uint4* ph = (uint4*)(smc + OPHI);
    uint4* pl = (uint4*)(smc + OPLO);
    uint4* ch_ = (uint4*)(smc + OCHI);
    uint4* cl_ = (uint4*)(smc + OCLO);
    const uint4* gh = g_ctx_hi + bh * 2048;
    const uint4* gl = g_ctx_lo + bh * 2048;
#pragma unroll
    for (int i = tid; i < 2048; i += 256) {
      ph[i] = g_proj_hi[i];
      pl[i] = g_proj_lo[i];
      ch_[i] = gh[i];
      cl_[i] = gl[i];
    }
  }
  ks_s[tid] = g_ksum[bh * NF_ + tid];
  ks_s[tid + 128] = g_ksum[bh * NF_ + tid + 128];

  for (int half = 0; half < 2; half++) {
    const int t0 = blockIdx.x * 256 + half * 128;
    if (half) __syncthreads();   // all warps past their ldmatrix of q before overwrite

    // --- q [128][64] -> bf16 hi/lo + per-row |q|^2 ---
    {
      const int rq = tid >> 1, hf = tid & 1;
      const float4* qg = (const float4*)(qin + ((size_t)(bh * T_ + t0 + rq)) * DH_);
      float dsum = 0.f;
#pragma unroll
      for (int c = 0; c < 8; c++) {
        float4 v = qg[hf*8 + c];
        dsum += v.x*v.x + v.y*v.y + v.z*v.z + v.w*v.w;
        int kp = hf*32 + c*4;
        uint32_t off = (uint32_t)rq*128 + (uint32_t)(((kp>>3) ^ (rq&7)) << 4)
                     + (uint32_t)((kp&7)*2);
        uint2 hi, lo; cvt_hilo(v, hi, lo);
        *(uint2*)(smc + OQHI + off) = hi;
        *(uint2*)(smc + OQLO + off) = lo;
      }
      dsum += __shfl_xor_sync(0xffffffff, dsum, 1);
      if (hf == 0) dn_s[rq] = dsum;
    }
    __syncthreads();

    const int r0 = warp * 16;
    uint32_t aq_hi[4][4], aq_lo[4][4];
#pragma unroll
    for (int kc = 0; kc < 4; kc++) {
      int row = r0 + ((lg & 1) << 3) + li;
      int ch  = kc*2 + (lg >> 1);
      uint32_t off = (uint32_t)row*128 + (uint32_t)(((ch ^ li) & 7) << 4);
      ldmx4(aq_hi[kc], sb + OQHI + off);
      ldmx4(aq_lo[kc], sb + OQLO + off);
    }

    float oacc[8][4];
#pragma unroll
    for (int et = 0; et < 8; et++)
#pragma unroll
      for (int i = 0; i < 4; i++) oacc[et][i] = 0.f;

    float den0 = 0.f, den1 = 0.f;
    const float dnt0 = DNC * dn_s[r0 + grp];
    const float dnt1 = DNC * dn_s[r0 + grp + 8];

    for (int jt = 0; jt < 16; jt++) {
      const int j0 = jt * 16;
      float x0[4] = {0,0,0,0}, y0[4] = {0,0,0,0};
      float x1[4] = {0,0,0,0}, y1[4] = {0,0,0,0};
#pragma unroll
      for (int kc = 0; kc < 4; kc++) {
        int row = j0 + ((lg >> 1) << 3) + li;
        int ch  = kc*2 + (lg & 1);
        uint32_t off = (uint32_t)row*128 + (uint32_t)(((ch ^ li) & 7) << 4);
        uint32_t bh_[4], bl_[4];
        ldmx4(bh_, sb + OPHI + off);
        ldmx4(bl_, sb + OPLO + off);
        mma_bf16(x0, aq_hi[kc], bh_ + 0, x0);
        mma_bf16(y0, aq_lo[kc], bh_ + 0, y0);
        mma_bf16(y0, aq_hi[kc], bl_ + 0, y0);
        mma_bf16(x1, aq_hi[kc], bh_ + 2, x1);
        mma_bf16(y1, aq_lo[kc], bh_ + 2, y1);
        mma_bf16(y1, aq_hi[kc], bl_ + 2, y1);
      }

      float e00 = __expf(fmaf(DS, x0[0] + y0[0], -dnt0));
      float e01 = __expf(fmaf(DS, x0[1] + y0[1], -dnt0));
      float e02 = __expf(fmaf(DS, x0[2] + y0[2], -dnt1));
      float e03 = __expf(fmaf(DS, x0[3] + y0[3], -dnt1));
      float e10 = __expf(fmaf(DS, x1[0] + y1[0], -dnt0));
      float e11 = __expf(fmaf(DS, x1[1] + y1[1], -dnt0));
      float e12 = __expf(fmaf(DS, x1[2] + y1[2], -dnt1));
      float e13 = __expf(fmaf(DS, x1[3] + y1[3], -dnt1));

      float2 kv0 = *(float2*)(ks_s + j0 + qd*2);
      float2 kv1 = *(float2*)(ks_s + j0 + 8 + qd*2);
      den0 = fmaf(e00, kv0.x, fmaf(e01, kv0.y, fmaf(e10, kv1.x, fmaf(e11, kv1.y, den0))));
      den1 = fmaf(e02, kv0.x, fmaf(e03, kv0.y, fmaf(e12, kv1.x, fmaf(e13, kv1.y, den1))));

      __nv_bfloat16 h00 = __float2bfloat16(e00), h01 = __float2bfloat16(e01);
      __nv_bfloat16 h02 = __float2bfloat16(e02), h03 = __float2bfloat16(e03);
      __nv_bfloat16 h10 = __float2bfloat16(e10), h11 = __float2bfloat16(e11);
      __nv_bfloat16 h12 = __float2bfloat16(e12), h13 = __float2bfloat16(e13);
      uint32_t qa_hi[4] = { packb(h00, h01), packb(h02, h03),
                            packb(h10, h11), packb(h12, h13) };
      uint32_t qa_lo[4] = {
        packb(__float2bfloat16(e00 - __bfloat162float(h00)),
              __float2bfloat16(e01 - __bfloat162float(h01))),
        packb(__float2bfloat16(e02 - __bfloat162float(h02)),
              __float2bfloat16(e03 - __bfloat162float(h03))),
        packb(__float2bfloat16(e10 - __bfloat162float(h10)),
              __float2bfloat16(e11 - __bfloat162float(h11))),
        packb(__float2bfloat16(e12 - __bfloat162float(h12)),
              __float2bfloat16(e13 - __bfloat162float(h13))) };

      const int ch0 = jt * 2;
#pragma unroll
      for (int etp = 0; etp < 4; etp++) {
        uint32_t bh_[4], bl_[4];
        int e = (etp*2 + (lg >> 1))*8 + li;
        int ch = ch0 + (lg & 1);
        uint32_t off = (uint32_t)e*512
                     + (uint32_t)((((ch & 24) | ((ch ^ li) & 7))) << 4);
        ldmx4(bh_, sb + OCHI + off);
        ldmx4(bl_, sb + OCLO + off);
        int et0 = etp*2, et1 = etp*2 + 1;
        mma_bf16(oacc[et0], qa_hi, bh_ + 0, oacc[et0]);
        mma_bf16(oacc[et0], qa_lo, bh_ + 0, oacc[et0]);
        mma_bf16(oacc[et0], qa_hi, bl_ + 0, oacc[et0]);
        mma_bf16(oacc[et1], qa_hi, bh_ + 2, oacc[et1]);
        mma_bf16(oacc[et1], qa_lo, bh_ + 2, oacc[et1]);
        mma_bf16(oacc[et1], qa_hi, bl_ + 2, oacc[et1]);
      }
    }

    den0 += __shfl_xor_sync(0xffffffff, den0, 1);
    den0 += __shfl_xor_sync(0xffffffff, den0, 2);
    den1 += __shfl_xor_sync(0xffffffff, den1, 1);
    den1 += __shfl_xor_sync(0xffffffff, den1, 2);
    float inv0 = 1.f / den0, inv1 = 1.f / den1;

    float* og0 = outg + ((size_t)(bh * T_ + t0 + r0 + grp)) * DH_;
    float* og1 = og0 + 8 * DH_;
#pragma unroll
    for (int et = 0; et < 8; et++) {
      int col = et * 8 + qd * 2;
      *(float2*)(og0 + col) = make_float2(oacc[et][0] * inv0, oacc[et][1] * inv0);
      *(float2*)(og1 + col) = make_float2(oacc[et][2] * inv1, oacc[et][3] * inv1);
    }
  }
}

// ---------------------------------------------------------------------------
extern "C" void kernel_launch(void* const* d_in, const int* in_sizes, int n_in,
                              void* d_out, int out_size) {
  const float* q    = (const float*)d_in[0];
  const float* k    = (const float*)d_in[1];
  const float* v    = (const float*)d_in[2];
  const float* proj = (const float*)d_in[3];
  float* out = (float*)d_out;

  cudaFuncSetAttribute(kernelAB, cudaFuncAttributeMaxDynamicSharedMemorySize, SMEMAB);
  cudaFuncSetAttribute(kernelC,  cudaFuncAttributeMaxDynamicSharedMemorySize, SMEMC);

  prep_proj<<<8, 256>>>(proj);
  kernelAB<<<dim3(16, BH_), 256, SMEMAB>>>(k, v);
  reduce_kernel<<<576, 256>>>();
  kernelC<<<dim3(T_/256, BH_), 256, SMEMC>>>(q, out);
}